// round 3
// baseline (speedup 1.0000x reference)
#include <cuda_runtime.h>
#include <cstdint>

#define MAXN 40000
#define MAXE 1048576
#define FDIM 128

// Static scratch (no allocation allowed)
__device__ int   g_degi  [MAXN];
__device__ float g_sumw  [MAXN];
__device__ float g_scales[2 * MAXN];   // [0,N): sm   [N,2N): sh
__device__ int   g_off   [MAXN + 1];
__device__ int   g_cursor[MAXN];
__device__ int2  g_epack [MAXE];       // .x = src, .y = float bits of w
__device__ float g_X  [MAXN * FDIM];
__device__ float g_h1 [MAXN * FDIM];
__device__ float g_h2 [MAXN * FDIM];

// ---------------------------------------------------------------------------
__global__ void zero_stats_kernel(int n) {
    int i = blockIdx.x * blockDim.x + threadIdx.x;
    if (i < n) { g_degi[i] = 0; g_sumw[i] = 0.f; }
}

__global__ void edge_stats_kernel(const int* __restrict__ dst,
                                  const float* __restrict__ w, int E) {
    int e = blockIdx.x * blockDim.x + threadIdx.x;
    if (e >= E) return;
    int d = dst[e];
    atomicAdd(&g_degi[d], 1);
    atomicAdd(&g_sumw[d], w[e]);
}

// Single-block exclusive scan of g_degi -> g_off/g_cursor, plus scales.
__global__ void __launch_bounds__(1024)
scan_scales_kernel(int n) {
    __shared__ int part[1024];
    int tid = threadIdx.x;
    int chunk = (n + 1023) >> 10;
    int begin = tid * chunk;
    int end   = min(begin + chunk, n);
    int s = 0;
    for (int i = begin; i < end; i++) s += g_degi[i];
    part[tid] = s;
    __syncthreads();
    // Hillis-Steele inclusive scan
    for (int d = 1; d < 1024; d <<= 1) {
        int v = (tid >= d) ? part[tid - d] : 0;
        __syncthreads();
        part[tid] += v;
        __syncthreads();
    }
    int run = (tid > 0) ? part[tid - 1] : 0;
    for (int i = begin; i < end; i++) {
        g_off[i]    = run;
        g_cursor[i] = run;
        int dg = g_degi[i];
        run += dg;
        // scales
        float dgf = (float)dg;
        float smv = 0.f, shv = 0.f;
        if (dg > 0) {
            float inv = 1.0f / (dgf + 1.0f);
            shv = inv;
            float sw = g_sumw[i];
            float swp = (sw == 0.f) ? 1.f : sw;
            smv = dgf * inv / swp;
        }
        g_scales[i]     = smv;
        g_scales[n + i] = shv;
    }
    if (begin < n && end == n) g_off[n] = run;
}

// Bucket edges by dst: epack[pos] = (src, w)
__global__ void scatter_kernel(const int* __restrict__ src,
                               const int* __restrict__ dst,
                               const float* __restrict__ w, int E) {
    int e = blockIdx.x * blockDim.x + threadIdx.x;
    if (e >= E) return;
    int d = dst[e];
    int pos = atomicAdd(&g_cursor[d], 1);
    g_epack[pos] = make_int2(src[e], __float_as_int(w[e]));
}

// Warp-per-node CSR aggregate + scale-combine:
//   X[node] = sm * sum_{e in in(node)} h[src_e]*w_e + sh * h[node]
__global__ void __launch_bounds__(256)
agg_csr_kernel(const float4* __restrict__ h, float4* __restrict__ X, int n) {
    int node = (blockIdx.x * blockDim.x + threadIdx.x) >> 5;
    int lane = threadIdx.x & 31;
    if (node >= n) return;
    int start = g_off[node];
    int end   = g_off[node + 1];
    float4 acc = make_float4(0.f, 0.f, 0.f, 0.f);
    int e = start;
    for (; e + 2 <= end; e += 2) {
        int2 p0 = g_epack[e];
        int2 p1 = g_epack[e + 1];
        float4 v0 = h[p0.x * 32 + lane];
        float4 v1 = h[p1.x * 32 + lane];
        float w0 = __int_as_float(p0.y);
        float w1 = __int_as_float(p1.y);
        acc.x = fmaf(v0.x, w0, fmaf(v1.x, w1, acc.x));
        acc.y = fmaf(v0.y, w0, fmaf(v1.y, w1, acc.y));
        acc.z = fmaf(v0.z, w0, fmaf(v1.z, w1, acc.z));
        acc.w = fmaf(v0.w, w0, fmaf(v1.w, w1, acc.w));
    }
    if (e < end) {
        int2 p = g_epack[e];
        float4 v = h[p.x * 32 + lane];
        float wt = __int_as_float(p.y);
        acc.x = fmaf(v.x, wt, acc.x);
        acc.y = fmaf(v.y, wt, acc.y);
        acc.z = fmaf(v.z, wt, acc.z);
        acc.w = fmaf(v.w, wt, acc.w);
    }
    float sm = g_scales[node];
    float sh = g_scales[n + node];
    float4 self = h[node * 32 + lane];
    float4 o;
    o.x = sm * acc.x + sh * self.x;
    o.y = sm * acc.y + sh * self.y;
    o.z = sm * acc.z + sh * self.z;
    o.w = sm * acc.w + sh * self.w;
    X[node * 32 + lane] = o;
}

// ---------------------------------------------------------------------------
// FFMA update (R1 version): hout = relu(X @ W^T + b)
// Tile: 32 nodes x 128 outs. Ws transposed pitch 132 (conflict-free float4).
#define WPITCH 132
__global__ void __launch_bounds__(256)
update_kernel(const float* __restrict__ X,
              const float* __restrict__ W,     // [128,128] row-major [o][k]
              const float* __restrict__ bias,  // [128]
              float* __restrict__ hout,        // [N,128]
              int n) {
    extern __shared__ float smem[];
    float* Ws = smem;                 // 128 * 132
    float* Xs = smem + FDIM * WPITCH; // 32 * 128
    int tid = threadIdx.x;

    for (int i = tid; i < FDIM * FDIM; i += 256) {
        int o = i >> 7, k = i & 127;
        Ws[k * WPITCH + o] = W[i];
    }

    int lane = tid & 31;
    int wp   = tid >> 5;
    float4 bv = *reinterpret_cast<const float4*>(&bias[lane * 4]);

    int ntiles = n >> 5;
    for (int tile = blockIdx.x; tile < ntiles; tile += gridDim.x) {
        __syncthreads();
        int n0 = tile << 5;
        for (int i = tid; i < 32 * FDIM; i += 256)
            Xs[i] = X[n0 * FDIM + i];
        __syncthreads();

        float acc[4][4];
#pragma unroll
        for (int j = 0; j < 4; j++) {
            acc[j][0] = bv.x; acc[j][1] = bv.y;
            acc[j][2] = bv.z; acc[j][3] = bv.w;
        }
#pragma unroll 4
        for (int k = 0; k < FDIM; k++) {
            float4 wv = *reinterpret_cast<const float4*>(&Ws[k * WPITCH + lane * 4]);
#pragma unroll
            for (int j = 0; j < 4; j++) {
                float xv = Xs[((wp << 2) + j) * FDIM + k];
                acc[j][0] += xv * wv.x;
                acc[j][1] += xv * wv.y;
                acc[j][2] += xv * wv.z;
                acc[j][3] += xv * wv.w;
            }
        }
#pragma unroll
        for (int j = 0; j < 4; j++) {
            int node = n0 + (wp << 2) + j;
            float4 r;
            r.x = fmaxf(acc[j][0], 0.f);
            r.y = fmaxf(acc[j][1], 0.f);
            r.z = fmaxf(acc[j][2], 0.f);
            r.w = fmaxf(acc[j][3], 0.f);
            *reinterpret_cast<float4*>(&hout[node * FDIM + lane * 4]) = r;
        }
    }
}

// Final classifier: out = h2 @ Wo^T + bo   ([N,128] x [32,128]^T -> [N,32])
__global__ void __launch_bounds__(256)
out_kernel(const float4* __restrict__ h2,
           const float* __restrict__ Wo, const float* __restrict__ bo,
           float* __restrict__ out, int n) {
    __shared__ float Wos[FDIM * 32];  // [k][o]
    int tid = threadIdx.x;
    for (int i = tid; i < 32 * FDIM; i += 256) {
        int o = i >> 7, k = i & 127;
        Wos[k * 32 + o] = Wo[i];
    }
    __syncthreads();

    int lane = tid & 31;
    int wp   = tid >> 5;
    float bias = bo[lane];
    for (int node = blockIdx.x * 8 + wp; node < n; node += gridDim.x * 8) {
        float4 x = h2[node * 32 + lane];
        float acc = bias;
#pragma unroll
        for (int j = 0; j < 32; j++) {
            float a = __shfl_sync(0xffffffffu, x.x, j);
            float b = __shfl_sync(0xffffffffu, x.y, j);
            float c = __shfl_sync(0xffffffffu, x.z, j);
            float d = __shfl_sync(0xffffffffu, x.w, j);
            int k = j << 2;
            acc += a * Wos[(k + 0) * 32 + lane];
            acc += b * Wos[(k + 1) * 32 + lane];
            acc += c * Wos[(k + 2) * 32 + lane];
            acc += d * Wos[(k + 3) * 32 + lane];
        }
        out[node * 32 + lane] = acc;
    }
}

// ---------------------------------------------------------------------------
extern "C" void kernel_launch(void* const* d_in, const int* in_sizes, int n_in,
                              void* d_out, int out_size) {
    const float* features = (const float*)d_in[0];
    const int*   src      = (const int*)  d_in[1];
    const int*   dst      = (const int*)  d_in[2];
    const float* weight   = (const float*)d_in[3];
    const float* W1       = (const float*)d_in[4];
    const float* b1       = (const float*)d_in[5];
    const float* W2       = (const float*)d_in[6];
    const float* b2       = (const float*)d_in[7];
    const float* Wo       = (const float*)d_in[8];
    const float* bo       = (const float*)d_in[9];
    float* out = (float*)d_out;

    int N = in_sizes[0] / FDIM;
    int E = in_sizes[1];

    void *pX_v, *ph1_v, *ph2_v;
    cudaGetSymbolAddress(&pX_v,  g_X);
    cudaGetSymbolAddress(&ph1_v, g_h1);
    cudaGetSymbolAddress(&ph2_v, g_h2);
    float* pX  = (float*)pX_v;
    float* ph1 = (float*)ph1_v;
    float* ph2 = (float*)ph2_v;

    const int smem_bytes = (FDIM * WPITCH + 32 * FDIM) * (int)sizeof(float); // 83968
    cudaFuncSetAttribute(update_kernel,
                         cudaFuncAttributeMaxDynamicSharedMemorySize, smem_bytes);

    // CSR build (shared by both layers)
    zero_stats_kernel<<<(N + 255) / 256, 256>>>(N);
    edge_stats_kernel<<<(E + 255) / 256, 256>>>(dst, weight, E);
    scan_scales_kernel<<<1, 1024>>>(N);
    scatter_kernel<<<(E + 255) / 256, 256>>>(src, dst, weight, E);

    int agg_grid = (N * 32 + 255) / 256;

    // Layer 1
    agg_csr_kernel<<<agg_grid, 256>>>((const float4*)features, (float4*)pX, N);
    update_kernel<<<304, 256, smem_bytes>>>(pX, W1, b1, ph1, N);

    // Layer 2
    agg_csr_kernel<<<agg_grid, 256>>>((const float4*)ph1, (float4*)pX, N);
    update_kernel<<<304, 256, smem_bytes>>>(pX, W2, b2, ph2, N);

    // Classifier
    out_kernel<<<2048, 256>>>((const float4*)ph2, Wo, bo, out, N);
}

// round 4
// speedup vs baseline: 1.0270x; 1.0270x over previous
#include <cuda_runtime.h>
#include <cstdint>

#define MAXN 40000
#define MAXE 1048576
#define FDIM 128

// Static scratch (no allocation allowed)
__device__ int   g_degi  [MAXN];
__device__ float g_sumw  [MAXN];
__device__ float g_scales[2 * MAXN];   // [0,N): sm   [N,2N): sh
__device__ int   g_off   [MAXN + 1];
__device__ int   g_cursor[MAXN];
__device__ int2  g_epack [MAXE];       // .x = src, .y = float bits of w
__device__ float g_X  [MAXN * FDIM];
__device__ float g_h1 [MAXN * FDIM];
__device__ float g_h2 [MAXN * FDIM];

// ---------------------------------------------------------------------------
__global__ void zero_stats_kernel(int n) {
    int i = blockIdx.x * blockDim.x + threadIdx.x;
    if (i < n) { g_degi[i] = 0; g_sumw[i] = 0.f; }
}

__global__ void edge_stats_kernel(const int* __restrict__ dst,
                                  const float* __restrict__ w, int E) {
    int e = blockIdx.x * blockDim.x + threadIdx.x;
    if (e >= E) return;
    int d = dst[e];
    atomicAdd(&g_degi[d], 1);
    atomicAdd(&g_sumw[d], w[e]);
}

// Single-block exclusive scan of g_degi -> g_off/g_cursor, plus scales.
__global__ void __launch_bounds__(1024)
scan_scales_kernel(int n) {
    __shared__ int part[1024];
    int tid = threadIdx.x;
    int chunk = (n + 1023) >> 10;
    int begin = tid * chunk;
    int end   = min(begin + chunk, n);
    int s = 0;
    for (int i = begin; i < end; i++) s += g_degi[i];
    part[tid] = s;
    __syncthreads();
    for (int d = 1; d < 1024; d <<= 1) {
        int v = (tid >= d) ? part[tid - d] : 0;
        __syncthreads();
        part[tid] += v;
        __syncthreads();
    }
    int run = (tid > 0) ? part[tid - 1] : 0;
    for (int i = begin; i < end; i++) {
        g_off[i]    = run;
        g_cursor[i] = run;
        int dg = g_degi[i];
        run += dg;
        float dgf = (float)dg;
        float smv = 0.f, shv = 0.f;
        if (dg > 0) {
            float inv = 1.0f / (dgf + 1.0f);
            shv = inv;
            float sw = g_sumw[i];
            float swp = (sw == 0.f) ? 1.f : sw;
            smv = dgf * inv / swp;
        }
        g_scales[i]     = smv;
        g_scales[n + i] = shv;
    }
    if (begin < n && end == n) g_off[n] = run;
}

// Bucket edges by dst: epack[pos] = (src, w)
__global__ void scatter_kernel(const int* __restrict__ src,
                               const int* __restrict__ dst,
                               const float* __restrict__ w, int E) {
    int e = blockIdx.x * blockDim.x + threadIdx.x;
    if (e >= E) return;
    int d = dst[e];
    int pos = atomicAdd(&g_cursor[d], 1);
    g_epack[pos] = make_int2(src[e], __float_as_int(w[e]));
}

// Warp-per-node CSR aggregate with 8-edge batched prefetch:
//   X[node] = sm * sum_{e in in(node)} h[src_e]*w_e + sh * h[node]
// Invalid chunk slots are padded with (s=0, w=0): unconditional loads keep
// all 8 gathers in flight (MLP=8), the zero weight makes them no-ops.
__global__ void __launch_bounds__(256)
agg_csr_kernel(const float4* __restrict__ h, float4* __restrict__ X, int n) {
    int node = (blockIdx.x * blockDim.x + threadIdx.x) >> 5;
    int lane = threadIdx.x & 31;
    if (node >= n) return;
    int start = g_off[node];
    int end   = g_off[node + 1];
    float4 acc = make_float4(0.f, 0.f, 0.f, 0.f);
    const unsigned FULL = 0xffffffffu;
    for (int base = start; base < end; base += 8) {
        int idx = base + (lane & 7);
        int2 p = make_int2(0, 0);
        if (idx < end) p = g_epack[idx];
        int s0 = __shfl_sync(FULL, p.x, 0), w0i = __shfl_sync(FULL, p.y, 0);
        int s1 = __shfl_sync(FULL, p.x, 1), w1i = __shfl_sync(FULL, p.y, 1);
        int s2 = __shfl_sync(FULL, p.x, 2), w2i = __shfl_sync(FULL, p.y, 2);
        int s3 = __shfl_sync(FULL, p.x, 3), w3i = __shfl_sync(FULL, p.y, 3);
        int s4 = __shfl_sync(FULL, p.x, 4), w4i = __shfl_sync(FULL, p.y, 4);
        int s5 = __shfl_sync(FULL, p.x, 5), w5i = __shfl_sync(FULL, p.y, 5);
        int s6 = __shfl_sync(FULL, p.x, 6), w6i = __shfl_sync(FULL, p.y, 6);
        int s7 = __shfl_sync(FULL, p.x, 7), w7i = __shfl_sync(FULL, p.y, 7);
        // 8 independent gathers
        float4 v0 = h[s0 * 32 + lane];
        float4 v1 = h[s1 * 32 + lane];
        float4 v2 = h[s2 * 32 + lane];
        float4 v3 = h[s3 * 32 + lane];
        float4 v4 = h[s4 * 32 + lane];
        float4 v5 = h[s5 * 32 + lane];
        float4 v6 = h[s6 * 32 + lane];
        float4 v7 = h[s7 * 32 + lane];
        float w0 = __int_as_float(w0i), w1 = __int_as_float(w1i);
        float w2 = __int_as_float(w2i), w3 = __int_as_float(w3i);
        float w4 = __int_as_float(w4i), w5 = __int_as_float(w5i);
        float w6 = __int_as_float(w6i), w7 = __int_as_float(w7i);
        acc.x = fmaf(v0.x, w0, acc.x); acc.y = fmaf(v0.y, w0, acc.y);
        acc.z = fmaf(v0.z, w0, acc.z); acc.w = fmaf(v0.w, w0, acc.w);
        acc.x = fmaf(v1.x, w1, acc.x); acc.y = fmaf(v1.y, w1, acc.y);
        acc.z = fmaf(v1.z, w1, acc.z); acc.w = fmaf(v1.w, w1, acc.w);
        acc.x = fmaf(v2.x, w2, acc.x); acc.y = fmaf(v2.y, w2, acc.y);
        acc.z = fmaf(v2.z, w2, acc.z); acc.w = fmaf(v2.w, w2, acc.w);
        acc.x = fmaf(v3.x, w3, acc.x); acc.y = fmaf(v3.y, w3, acc.y);
        acc.z = fmaf(v3.z, w3, acc.z); acc.w = fmaf(v3.w, w3, acc.w);
        acc.x = fmaf(v4.x, w4, acc.x); acc.y = fmaf(v4.y, w4, acc.y);
        acc.z = fmaf(v4.z, w4, acc.z); acc.w = fmaf(v4.w, w4, acc.w);
        acc.x = fmaf(v5.x, w5, acc.x); acc.y = fmaf(v5.y, w5, acc.y);
        acc.z = fmaf(v5.z, w5, acc.z); acc.w = fmaf(v5.w, w5, acc.w);
        acc.x = fmaf(v6.x, w6, acc.x); acc.y = fmaf(v6.y, w6, acc.y);
        acc.z = fmaf(v6.z, w6, acc.z); acc.w = fmaf(v6.w, w6, acc.w);
        acc.x = fmaf(v7.x, w7, acc.x); acc.y = fmaf(v7.y, w7, acc.y);
        acc.z = fmaf(v7.z, w7, acc.z); acc.w = fmaf(v7.w, w7, acc.w);
    }
    float sm = g_scales[node];
    float sh = g_scales[n + node];
    float4 self = h[node * 32 + lane];
    float4 o;
    o.x = fmaf(sm, acc.x, sh * self.x);
    o.y = fmaf(sm, acc.y, sh * self.y);
    o.z = fmaf(sm, acc.z, sh * self.z);
    o.w = fmaf(sm, acc.w, sh * self.w);
    X[node * 32 + lane] = o;
}

// ---------------------------------------------------------------------------
// FFMA update, 8-node register blocking: hout = relu(X @ W^T + b)
// Tile: 64 nodes x 128 outs per block. Warp wp owns nodes [8wp, 8wp+8),
// lane owns outs [4*lane, 4*lane+4). Per k: 1 LDS.128 + 8 bcast LDS + 32 FFMA.
#define TM 64
#define WPITCH 132
__global__ void __launch_bounds__(256)
update_kernel(const float4* __restrict__ X,
              const float* __restrict__ W,     // [128,128] row-major [o][k]
              const float* __restrict__ bias,  // [128]
              float* __restrict__ hout,        // [N,128]
              int n) {
    extern __shared__ float smem[];
    float* Ws = smem;                 // 128 * 132
    float* Xs = smem + FDIM * WPITCH; // 64 * 128
    int tid = threadIdx.x;

    for (int i = tid; i < FDIM * FDIM; i += 256) {
        int o = i >> 7, k = i & 127;
        Ws[k * WPITCH + o] = W[i];
    }

    int lane = tid & 31;
    int wp   = tid >> 5;
    float4 bv = *reinterpret_cast<const float4*>(&bias[lane * 4]);

    int ntiles = n / TM;
    for (int tile = blockIdx.x; tile < ntiles; tile += gridDim.x) {
        __syncthreads();
        int n0 = tile * TM;
        float4* Xs4 = reinterpret_cast<float4*>(Xs);
        for (int i = tid; i < TM * 32; i += 256)
            Xs4[i] = X[n0 * 32 + i];
        __syncthreads();

        float acc[8][4];
#pragma unroll
        for (int j = 0; j < 8; j++) {
            acc[j][0] = bv.x; acc[j][1] = bv.y;
            acc[j][2] = bv.z; acc[j][3] = bv.w;
        }
#pragma unroll 2
        for (int k = 0; k < FDIM; k++) {
            float4 wv = *reinterpret_cast<const float4*>(&Ws[k * WPITCH + lane * 4]);
#pragma unroll
            for (int j = 0; j < 8; j++) {
                float xv = Xs[((wp << 3) + j) * FDIM + k];
                acc[j][0] = fmaf(xv, wv.x, acc[j][0]);
                acc[j][1] = fmaf(xv, wv.y, acc[j][1]);
                acc[j][2] = fmaf(xv, wv.z, acc[j][2]);
                acc[j][3] = fmaf(xv, wv.w, acc[j][3]);
            }
        }
#pragma unroll
        for (int j = 0; j < 8; j++) {
            int node = n0 + (wp << 3) + j;
            float4 r;
            r.x = fmaxf(acc[j][0], 0.f);
            r.y = fmaxf(acc[j][1], 0.f);
            r.z = fmaxf(acc[j][2], 0.f);
            r.w = fmaxf(acc[j][3], 0.f);
            *reinterpret_cast<float4*>(&hout[node * FDIM + lane * 4]) = r;
        }
    }
}

// Final classifier: out = h2 @ Wo^T + bo   ([N,128] x [32,128]^T -> [N,32])
__global__ void __launch_bounds__(256)
out_kernel(const float4* __restrict__ h2,
           const float* __restrict__ Wo, const float* __restrict__ bo,
           float* __restrict__ out, int n) {
    __shared__ float Wos[FDIM * 32];  // [k][o]
    int tid = threadIdx.x;
    for (int i = tid; i < 32 * FDIM; i += 256) {
        int o = i >> 7, k = i & 127;
        Wos[k * 32 + o] = Wo[i];
    }
    __syncthreads();

    int lane = tid & 31;
    int wp   = tid >> 5;
    float bias = bo[lane];
    for (int node = blockIdx.x * 8 + wp; node < n; node += gridDim.x * 8) {
        float4 x = h2[node * 32 + lane];
        float acc = bias;
#pragma unroll
        for (int j = 0; j < 32; j++) {
            float a = __shfl_sync(0xffffffffu, x.x, j);
            float b = __shfl_sync(0xffffffffu, x.y, j);
            float c = __shfl_sync(0xffffffffu, x.z, j);
            float d = __shfl_sync(0xffffffffu, x.w, j);
            int k = j << 2;
            acc += a * Wos[(k + 0) * 32 + lane];
            acc += b * Wos[(k + 1) * 32 + lane];
            acc += c * Wos[(k + 2) * 32 + lane];
            acc += d * Wos[(k + 3) * 32 + lane];
        }
        out[node * 32 + lane] = acc;
    }
}

// ---------------------------------------------------------------------------
extern "C" void kernel_launch(void* const* d_in, const int* in_sizes, int n_in,
                              void* d_out, int out_size) {
    const float* features = (const float*)d_in[0];
    const int*   src      = (const int*)  d_in[1];
    const int*   dst      = (const int*)  d_in[2];
    const float* weight   = (const float*)d_in[3];
    const float* W1       = (const float*)d_in[4];
    const float* b1       = (const float*)d_in[5];
    const float* W2       = (const float*)d_in[6];
    const float* b2       = (const float*)d_in[7];
    const float* Wo       = (const float*)d_in[8];
    const float* bo       = (const float*)d_in[9];
    float* out = (float*)d_out;

    int N = in_sizes[0] / FDIM;
    int E = in_sizes[1];

    void *pX_v, *ph1_v, *ph2_v;
    cudaGetSymbolAddress(&pX_v,  g_X);
    cudaGetSymbolAddress(&ph1_v, g_h1);
    cudaGetSymbolAddress(&ph2_v, g_h2);
    float* pX  = (float*)pX_v;
    float* ph1 = (float*)ph1_v;
    float* ph2 = (float*)ph2_v;

    const int smem_bytes = (FDIM * WPITCH + TM * FDIM) * (int)sizeof(float); // ~100KB
    cudaFuncSetAttribute(update_kernel,
                         cudaFuncAttributeMaxDynamicSharedMemorySize, smem_bytes);

    // CSR build (shared by both layers)
    zero_stats_kernel<<<(N + 255) / 256, 256>>>(N);
    edge_stats_kernel<<<(E + 255) / 256, 256>>>(dst, weight, E);
    scan_scales_kernel<<<1, 1024>>>(N);
    scatter_kernel<<<(E + 255) / 256, 256>>>(src, dst, weight, E);

    int agg_grid = (N * 32 + 255) / 256;
    int upd_grid = 296;  // 2 blocks/SM, grid-stride over N/64 tiles

    // Layer 1
    agg_csr_kernel<<<agg_grid, 256>>>((const float4*)features, (float4*)pX, N);
    update_kernel<<<upd_grid, 256, smem_bytes>>>((const float4*)pX, W1, b1, ph1, N);

    // Layer 2
    agg_csr_kernel<<<agg_grid, 256>>>((const float4*)ph1, (float4*)pX, N);
    update_kernel<<<upd_grid, 256, smem_bytes>>>((const float4*)pX, W2, b2, ph2, N);

    // Classifier
    out_kernel<<<2048, 256>>>((const float4*)ph2, Wo, bo, out, N);
}

// round 5
// speedup vs baseline: 1.5211x; 1.4811x over previous
#include <cuda_runtime.h>
#include <cstdint>

#define MAXN 40000
#define MAXE 1048576
#define FDIM 128
#define SCAN_BLK 1024
#define MAX_PART 64   // ceil(MAXN/1024) = 40 <= 64

// Static scratch (no allocation allowed)
__device__ int   g_degi   [MAXN];
__device__ float g_sumw   [MAXN];
__device__ float g_scales [2 * MAXN];   // [0,N): sm   [N,2N): sh
__device__ int   g_off    [MAXN + 1];
__device__ int   g_cursor [MAXN];
__device__ int   g_part   [MAX_PART];
__device__ int   g_partoff[MAX_PART];
__device__ int2  g_epack  [MAXE];       // .x = src, .y = float bits of w
__device__ float g_X  [MAXN * FDIM];
__device__ float g_h1 [MAXN * FDIM];
__device__ float g_h2 [MAXN * FDIM];

// ---------------------------------------------------------------------------
__global__ void edge_stats_kernel(const int* __restrict__ dst,
                                  const float* __restrict__ w, int E) {
    int e = blockIdx.x * blockDim.x + threadIdx.x;
    if (e >= E) return;
    int d = dst[e];
    atomicAdd(&g_degi[d], 1);
    atomicAdd(&g_sumw[d], w[e]);
}

// Phase A: per-block partial sums of deg
__global__ void __launch_bounds__(SCAN_BLK)
scan_partial_kernel(int n) {
    __shared__ int sh[SCAN_BLK];
    int tid = threadIdx.x;
    int i = blockIdx.x * SCAN_BLK + tid;
    sh[tid] = (i < n) ? g_degi[i] : 0;
    __syncthreads();
    for (int d = SCAN_BLK / 2; d > 0; d >>= 1) {
        if (tid < d) sh[tid] += sh[tid + d];
        __syncthreads();
    }
    if (tid == 0) g_part[blockIdx.x] = sh[0];
}

// Phase B: scan the (<=64) partials; write total to g_off[n]
__global__ void scan_top_kernel(int nb, int n) {
    __shared__ int sh[MAX_PART];
    int tid = threadIdx.x;  // 64 threads
    int v = (tid < nb) ? g_part[tid] : 0;
    sh[tid] = v;
    __syncthreads();
    for (int d = 1; d < MAX_PART; d <<= 1) {
        int t = (tid >= d) ? sh[tid - d] : 0;
        __syncthreads();
        sh[tid] += t;
        __syncthreads();
    }
    if (tid < nb) g_partoff[tid] = sh[tid] - v;   // exclusive
    if (tid == 0) g_off[n] = sh[nb - 1];          // total edges
}

// Phase C: in-block scan + emit off/cursor + fused scales
__global__ void __launch_bounds__(SCAN_BLK)
scan_emit_kernel(int n) {
    __shared__ int sh[SCAN_BLK];
    int tid = threadIdx.x;
    int i = blockIdx.x * SCAN_BLK + tid;
    int dg = (i < n) ? g_degi[i] : 0;
    sh[tid] = dg;
    __syncthreads();
    for (int d = 1; d < SCAN_BLK; d <<= 1) {
        int t = (tid >= d) ? sh[tid - d] : 0;
        __syncthreads();
        sh[tid] += t;
        __syncthreads();
    }
    if (i < n) {
        int ex = sh[tid] - dg + g_partoff[blockIdx.x];
        g_off[i]    = ex;
        g_cursor[i] = ex;
        float dgf = (float)dg;
        float smv = 0.f, shv = 0.f;
        if (dg > 0) {
            float inv = 1.0f / (dgf + 1.0f);
            shv = inv;
            float sw = g_sumw[i];
            float swp = (sw == 0.f) ? 1.f : sw;
            smv = dgf * inv / swp;
        }
        g_scales[i]     = smv;
        g_scales[n + i] = shv;
    }
}

// Bucket edges by dst: epack[pos] = (src, w)
__global__ void scatter_kernel(const int* __restrict__ src,
                               const int* __restrict__ dst,
                               const float* __restrict__ w, int E) {
    int e = blockIdx.x * blockDim.x + threadIdx.x;
    if (e >= E) return;
    int d = dst[e];
    int pos = atomicAdd(&g_cursor[d], 1);
    g_epack[pos] = make_int2(src[e], __float_as_int(w[e]));
}

// Warp-per-node CSR aggregate with 8-edge batched prefetch:
//   X[node] = sm * sum_{e in in(node)} h[src_e]*w_e + sh * h[node]
__global__ void __launch_bounds__(256)
agg_csr_kernel(const float4* __restrict__ h, float4* __restrict__ X, int n) {
    int node = (blockIdx.x * blockDim.x + threadIdx.x) >> 5;
    int lane = threadIdx.x & 31;
    if (node >= n) return;
    int start = g_off[node];
    int end   = g_off[node + 1];
    float4 acc = make_float4(0.f, 0.f, 0.f, 0.f);
    const unsigned FULL = 0xffffffffu;
    for (int base = start; base < end; base += 8) {
        int idx = base + (lane & 7);
        int2 p = make_int2(0, 0);
        if (idx < end) p = g_epack[idx];
        int s0 = __shfl_sync(FULL, p.x, 0), w0i = __shfl_sync(FULL, p.y, 0);
        int s1 = __shfl_sync(FULL, p.x, 1), w1i = __shfl_sync(FULL, p.y, 1);
        int s2 = __shfl_sync(FULL, p.x, 2), w2i = __shfl_sync(FULL, p.y, 2);
        int s3 = __shfl_sync(FULL, p.x, 3), w3i = __shfl_sync(FULL, p.y, 3);
        int s4 = __shfl_sync(FULL, p.x, 4), w4i = __shfl_sync(FULL, p.y, 4);
        int s5 = __shfl_sync(FULL, p.x, 5), w5i = __shfl_sync(FULL, p.y, 5);
        int s6 = __shfl_sync(FULL, p.x, 6), w6i = __shfl_sync(FULL, p.y, 6);
        int s7 = __shfl_sync(FULL, p.x, 7), w7i = __shfl_sync(FULL, p.y, 7);
        float4 v0 = h[s0 * 32 + lane];
        float4 v1 = h[s1 * 32 + lane];
        float4 v2 = h[s2 * 32 + lane];
        float4 v3 = h[s3 * 32 + lane];
        float4 v4 = h[s4 * 32 + lane];
        float4 v5 = h[s5 * 32 + lane];
        float4 v6 = h[s6 * 32 + lane];
        float4 v7 = h[s7 * 32 + lane];
        float w0 = __int_as_float(w0i), w1 = __int_as_float(w1i);
        float w2 = __int_as_float(w2i), w3 = __int_as_float(w3i);
        float w4 = __int_as_float(w4i), w5 = __int_as_float(w5i);
        float w6 = __int_as_float(w6i), w7 = __int_as_float(w7i);
        acc.x = fmaf(v0.x, w0, acc.x); acc.y = fmaf(v0.y, w0, acc.y);
        acc.z = fmaf(v0.z, w0, acc.z); acc.w = fmaf(v0.w, w0, acc.w);
        acc.x = fmaf(v1.x, w1, acc.x); acc.y = fmaf(v1.y, w1, acc.y);
        acc.z = fmaf(v1.z, w1, acc.z); acc.w = fmaf(v1.w, w1, acc.w);
        acc.x = fmaf(v2.x, w2, acc.x); acc.y = fmaf(v2.y, w2, acc.y);
        acc.z = fmaf(v2.z, w2, acc.z); acc.w = fmaf(v2.w, w2, acc.w);
        acc.x = fmaf(v3.x, w3, acc.x); acc.y = fmaf(v3.y, w3, acc.y);
        acc.z = fmaf(v3.z, w3, acc.z); acc.w = fmaf(v3.w, w3, acc.w);
        acc.x = fmaf(v4.x, w4, acc.x); acc.y = fmaf(v4.y, w4, acc.y);
        acc.z = fmaf(v4.z, w4, acc.z); acc.w = fmaf(v4.w, w4, acc.w);
        acc.x = fmaf(v5.x, w5, acc.x); acc.y = fmaf(v5.y, w5, acc.y);
        acc.z = fmaf(v5.z, w5, acc.z); acc.w = fmaf(v5.w, w5, acc.w);
        acc.x = fmaf(v6.x, w6, acc.x); acc.y = fmaf(v6.y, w6, acc.y);
        acc.z = fmaf(v6.z, w6, acc.z); acc.w = fmaf(v6.w, w6, acc.w);
        acc.x = fmaf(v7.x, w7, acc.x); acc.y = fmaf(v7.y, w7, acc.y);
        acc.z = fmaf(v7.z, w7, acc.z); acc.w = fmaf(v7.w, w7, acc.w);
    }
    float sm = g_scales[node];
    float sh = g_scales[n + node];
    float4 self = h[node * 32 + lane];
    float4 o;
    o.x = fmaf(sm, acc.x, sh * self.x);
    o.y = fmaf(sm, acc.y, sh * self.y);
    o.z = fmaf(sm, acc.z, sh * self.z);
    o.w = fmaf(sm, acc.w, sh * self.w);
    X[node * 32 + lane] = o;
}

// ---------------------------------------------------------------------------
// FFMA update, 8-node register blocking: hout = relu(X @ W^T + b)
#define TM 64
#define WPITCH 132
__global__ void __launch_bounds__(256)
update_kernel(const float4* __restrict__ X,
              const float* __restrict__ W,     // [128,128] row-major [o][k]
              const float* __restrict__ bias,  // [128]
              float* __restrict__ hout,        // [N,128]
              int n) {
    extern __shared__ float smem[];
    float* Ws = smem;                 // 128 * 132
    float* Xs = smem + FDIM * WPITCH; // 64 * 128
    int tid = threadIdx.x;

    for (int i = tid; i < FDIM * FDIM; i += 256) {
        int o = i >> 7, k = i & 127;
        Ws[k * WPITCH + o] = W[i];
    }

    int lane = tid & 31;
    int wp   = tid >> 5;
    float4 bv = *reinterpret_cast<const float4*>(&bias[lane * 4]);

    int ntiles = n / TM;
    for (int tile = blockIdx.x; tile < ntiles; tile += gridDim.x) {
        __syncthreads();
        int n0 = tile * TM;
        float4* Xs4 = reinterpret_cast<float4*>(Xs);
        for (int i = tid; i < TM * 32; i += 256)
            Xs4[i] = X[n0 * 32 + i];
        __syncthreads();

        float acc[8][4];
#pragma unroll
        for (int j = 0; j < 8; j++) {
            acc[j][0] = bv.x; acc[j][1] = bv.y;
            acc[j][2] = bv.z; acc[j][3] = bv.w;
        }
#pragma unroll 2
        for (int k = 0; k < FDIM; k++) {
            float4 wv = *reinterpret_cast<const float4*>(&Ws[k * WPITCH + lane * 4]);
#pragma unroll
            for (int j = 0; j < 8; j++) {
                float xv = Xs[((wp << 3) + j) * FDIM + k];
                acc[j][0] = fmaf(xv, wv.x, acc[j][0]);
                acc[j][1] = fmaf(xv, wv.y, acc[j][1]);
                acc[j][2] = fmaf(xv, wv.z, acc[j][2]);
                acc[j][3] = fmaf(xv, wv.w, acc[j][3]);
            }
        }
#pragma unroll
        for (int j = 0; j < 8; j++) {
            int node = n0 + (wp << 3) + j;
            float4 r;
            r.x = fmaxf(acc[j][0], 0.f);
            r.y = fmaxf(acc[j][1], 0.f);
            r.z = fmaxf(acc[j][2], 0.f);
            r.w = fmaxf(acc[j][3], 0.f);
            *reinterpret_cast<float4*>(&hout[node * FDIM + lane * 4]) = r;
        }
    }
}

// Final classifier: out = h2 @ Wo^T + bo   ([N,128] x [32,128]^T -> [N,32])
__global__ void __launch_bounds__(256)
out_kernel(const float4* __restrict__ h2,
           const float* __restrict__ Wo, const float* __restrict__ bo,
           float* __restrict__ out, int n) {
    __shared__ float Wos[FDIM * 32];  // [k][o]
    int tid = threadIdx.x;
    for (int i = tid; i < 32 * FDIM; i += 256) {
        int o = i >> 7, k = i & 127;
        Wos[k * 32 + o] = Wo[i];
    }
    __syncthreads();

    int lane = tid & 31;
    int wp   = tid >> 5;
    float bias = bo[lane];
    for (int node = blockIdx.x * 8 + wp; node < n; node += gridDim.x * 8) {
        float4 x = h2[node * 32 + lane];
        float acc = bias;
#pragma unroll
        for (int j = 0; j < 32; j++) {
            float a = __shfl_sync(0xffffffffu, x.x, j);
            float b = __shfl_sync(0xffffffffu, x.y, j);
            float c = __shfl_sync(0xffffffffu, x.z, j);
            float d = __shfl_sync(0xffffffffu, x.w, j);
            int k = j << 2;
            acc += a * Wos[(k + 0) * 32 + lane];
            acc += b * Wos[(k + 1) * 32 + lane];
            acc += c * Wos[(k + 2) * 32 + lane];
            acc += d * Wos[(k + 3) * 32 + lane];
        }
        out[node * 32 + lane] = acc;
    }
}

// ---------------------------------------------------------------------------
extern "C" void kernel_launch(void* const* d_in, const int* in_sizes, int n_in,
                              void* d_out, int out_size) {
    const float* features = (const float*)d_in[0];
    const int*   src      = (const int*)  d_in[1];
    const int*   dst      = (const int*)  d_in[2];
    const float* weight   = (const float*)d_in[3];
    const float* W1       = (const float*)d_in[4];
    const float* b1       = (const float*)d_in[5];
    const float* W2       = (const float*)d_in[6];
    const float* b2       = (const float*)d_in[7];
    const float* Wo       = (const float*)d_in[8];
    const float* bo       = (const float*)d_in[9];
    float* out = (float*)d_out;

    int N = in_sizes[0] / FDIM;
    int E = in_sizes[1];

    void *pX_v, *ph1_v, *ph2_v, *pdeg_v, *psw_v;
    cudaGetSymbolAddress(&pX_v,  g_X);
    cudaGetSymbolAddress(&ph1_v, g_h1);
    cudaGetSymbolAddress(&ph2_v, g_h2);
    cudaGetSymbolAddress(&pdeg_v, g_degi);
    cudaGetSymbolAddress(&psw_v,  g_sumw);
    float* pX  = (float*)pX_v;
    float* ph1 = (float*)ph1_v;
    float* ph2 = (float*)ph2_v;

    const int smem_bytes = (FDIM * WPITCH + TM * FDIM) * (int)sizeof(float); // ~100KB
    cudaFuncSetAttribute(update_kernel,
                         cudaFuncAttributeMaxDynamicSharedMemorySize, smem_bytes);

    int nb = (N + SCAN_BLK - 1) / SCAN_BLK;   // <= 40

    // CSR build (shared by both layers)
    cudaMemsetAsync(pdeg_v, 0, N * sizeof(int));
    cudaMemsetAsync(psw_v,  0, N * sizeof(float));
    edge_stats_kernel<<<(E + 255) / 256, 256>>>(dst, weight, E);
    scan_partial_kernel<<<nb, SCAN_BLK>>>(N);
    scan_top_kernel<<<1, MAX_PART>>>(nb, N);
    scan_emit_kernel<<<nb, SCAN_BLK>>>(N);
    scatter_kernel<<<(E + 255) / 256, 256>>>(src, dst, weight, E);

    int agg_grid = (N * 32 + 255) / 256;
    int upd_grid = 296;

    // Layer 1
    agg_csr_kernel<<<agg_grid, 256>>>((const float4*)features, (float4*)pX, N);
    update_kernel<<<upd_grid, 256, smem_bytes>>>((const float4*)pX, W1, b1, ph1, N);

    // Layer 2
    agg_csr_kernel<<<agg_grid, 256>>>((const float4*)ph1, (float4*)pX, N);
    update_kernel<<<upd_grid, 256, smem_bytes>>>((const float4*)pX, W2, b2, ph2, N);

    // Classifier
    out_kernel<<<2048, 256>>>((const float4*)ph2, Wo, bo, out, N);
}

// round 7
// speedup vs baseline: 1.5559x; 1.0228x over previous
#include <cuda_runtime.h>
#include <cstdint>

#define MAXN 40000
#define MAXE 1048576
#define FDIM 128
#define SCAN_BLK 1024
#define MAX_PART 64

// Static scratch (no allocation allowed)
__device__ unsigned long long g_pack[MAXN];  // deg<<40 | sumw*2^20
__device__ float g_scales [2 * MAXN];        // [0,N): sm   [N,2N): sh
__device__ int   g_off    [MAXN + 1];
__device__ int   g_cursor [MAXN];
__device__ int   g_part   [MAX_PART];
__device__ int   g_partoff[MAX_PART];
__device__ int2  g_epack  [MAXE];            // .x = src, .y = float bits of w
__device__ float g_X  [MAXN * FDIM];
__device__ float g_h1 [MAXN * FDIM];
__device__ float g_h2 [MAXN * FDIM];

// ---------------------------------------------------------------------------
// deg and sumw in ONE 64-bit atomic: +(1<<40) + round(w * 2^20)
__global__ void edge_stats_kernel(const int* __restrict__ dst,
                                  const float* __restrict__ w, int E) {
    int e = blockIdx.x * blockDim.x + threadIdx.x;
    if (e >= E) return;
    unsigned long long add =
        (1ULL << 40) | (unsigned long long)__float2uint_rn(w[e] * 1048576.f);
    atomicAdd(&g_pack[dst[e]], add);
}

// Phase A: per-block partial sums of deg
__global__ void __launch_bounds__(SCAN_BLK)
scan_partial_kernel(int n) {
    __shared__ int sh[SCAN_BLK];
    int tid = threadIdx.x;
    int i = blockIdx.x * SCAN_BLK + tid;
    sh[tid] = (i < n) ? (int)(g_pack[i] >> 40) : 0;
    __syncthreads();
    for (int d = SCAN_BLK / 2; d > 0; d >>= 1) {
        if (tid < d) sh[tid] += sh[tid + d];
        __syncthreads();
    }
    if (tid == 0) g_part[blockIdx.x] = sh[0];
}

// Phase B: scan the (<=64) partials
__global__ void scan_top_kernel(int nb, int n) {
    __shared__ int sh[MAX_PART];
    int tid = threadIdx.x;
    int v = (tid < nb) ? g_part[tid] : 0;
    sh[tid] = v;
    __syncthreads();
    for (int d = 1; d < MAX_PART; d <<= 1) {
        int t = (tid >= d) ? sh[tid - d] : 0;
        __syncthreads();
        sh[tid] += t;
        __syncthreads();
    }
    if (tid < nb) g_partoff[tid] = sh[tid] - v;
    if (tid == 0) g_off[n] = sh[nb - 1];
}

// Phase C: in-block scan + emit off/cursor + fused scales
__global__ void __launch_bounds__(SCAN_BLK)
scan_emit_kernel(int n) {
    __shared__ int sh[SCAN_BLK];
    int tid = threadIdx.x;
    int i = blockIdx.x * SCAN_BLK + tid;
    unsigned long long pk = (i < n) ? g_pack[i] : 0ULL;
    int dg = (int)(pk >> 40);
    sh[tid] = dg;
    __syncthreads();
    for (int d = 1; d < SCAN_BLK; d <<= 1) {
        int t = (tid >= d) ? sh[tid - d] : 0;
        __syncthreads();
        sh[tid] += t;
        __syncthreads();
    }
    if (i < n) {
        int ex = sh[tid] - dg + g_partoff[blockIdx.x];
        g_off[i]    = ex;
        g_cursor[i] = ex;
        float sw = (float)(pk & ((1ULL << 40) - 1ULL)) * (1.0f / 1048576.f);
        float dgf = (float)dg;
        float smv = 0.f, shv = 0.f;
        if (dg > 0) {
            float inv = 1.0f / (dgf + 1.0f);
            shv = inv;
            float swp = (sw == 0.f) ? 1.f : sw;
            smv = dgf * inv / swp;
        }
        g_scales[i]     = smv;
        g_scales[n + i] = shv;
    }
}

__global__ void scatter_kernel(const int* __restrict__ src,
                               const int* __restrict__ dst,
                               const float* __restrict__ w, int E) {
    int e = blockIdx.x * blockDim.x + threadIdx.x;
    if (e >= E) return;
    int d = dst[e];
    int pos = atomicAdd(&g_cursor[d], 1);
    g_epack[pos] = make_int2(src[e], __float_as_int(w[e]));
}

// Warp-per-node CSR aggregate. 8-edge batches: explicit v[8] gather array
// (all 8 LDG.128 issued before any FMA -> MLP=8, predicated on validity),
// plus software prefetch of the next epack chunk.
__global__ void __launch_bounds__(256)
agg_csr_kernel(const float4* __restrict__ h, float4* __restrict__ X, int n) {
    int node = (blockIdx.x * blockDim.x + threadIdx.x) >> 5;
    int lane = threadIdx.x & 31;
    if (node >= n) return;
    int start = g_off[node];
    int end   = g_off[node + 1];
    float4 acc = make_float4(0.f, 0.f, 0.f, 0.f);
    const unsigned FULL = 0xffffffffu;
    int l8 = lane & 7;
    int idx0 = start + l8;
    int2 p = (idx0 < end) ? g_epack[idx0] : make_int2(0, 0);
    for (int base = start; base < end; base += 8) {
        int2 cur = p;
        int nidx = base + 8 + l8;
        p = (nidx < end) ? g_epack[nidx] : make_int2(0, 0);

        int   ss[8];
        float ww[8];
#pragma unroll
        for (int j = 0; j < 8; j++) {
            ss[j] = __shfl_sync(FULL, cur.x, j);
            ww[j] = __int_as_float(__shfl_sync(FULL, cur.y, j));
        }
        float4 v[8];
#pragma unroll
        for (int j = 0; j < 8; j++)
            v[j] = (base + j < end) ? h[ss[j] * 32 + lane]
                                    : make_float4(0.f, 0.f, 0.f, 0.f);
#pragma unroll
        for (int j = 0; j < 8; j++) {
            acc.x = fmaf(v[j].x, ww[j], acc.x);
            acc.y = fmaf(v[j].y, ww[j], acc.y);
            acc.z = fmaf(v[j].z, ww[j], acc.z);
            acc.w = fmaf(v[j].w, ww[j], acc.w);
        }
    }
    float sm = g_scales[node];
    float sh = g_scales[n + node];
    float4 self = h[node * 32 + lane];
    float4 o;
    o.x = fmaf(sm, acc.x, sh * self.x);
    o.y = fmaf(sm, acc.y, sh * self.y);
    o.z = fmaf(sm, acc.z, sh * self.z);
    o.w = fmaf(sm, acc.w, sh * self.w);
    X[node * 32 + lane] = o;
}

// ---------------------------------------------------------------------------
// FFMA update, 8-node register blocking (R5-proven): hout = relu(X@W^T + b)
#define TM 64
#define WPITCH 132
__global__ void __launch_bounds__(256)
update_kernel(const float4* __restrict__ X,
              const float* __restrict__ W,     // [128,128] row-major [o][k]
              const float* __restrict__ bias,
              float* __restrict__ hout, int n) {
    extern __shared__ float smem[];
    float* Ws = smem;                 // 128 * 132
    float* Xs = smem + FDIM * WPITCH; // 64 * 128
    int tid = threadIdx.x;

    for (int i = tid; i < FDIM * FDIM; i += 256) {
        int o = i >> 7, k = i & 127;
        Ws[k * WPITCH + o] = W[i];
    }

    int lane = tid & 31;
    int wp   = tid >> 5;
    float4 bv = *reinterpret_cast<const float4*>(&bias[lane * 4]);

    int ntiles = n / TM;
    for (int tile = blockIdx.x; tile < ntiles; tile += gridDim.x) {
        __syncthreads();
        int n0 = tile * TM;
        float4* Xs4 = reinterpret_cast<float4*>(Xs);
        for (int i = tid; i < TM * 32; i += 256)
            Xs4[i] = X[n0 * 32 + i];
        __syncthreads();

        float acc[8][4];
#pragma unroll
        for (int j = 0; j < 8; j++) {
            acc[j][0] = bv.x; acc[j][1] = bv.y;
            acc[j][2] = bv.z; acc[j][3] = bv.w;
        }
#pragma unroll 2
        for (int k = 0; k < FDIM; k++) {
            float4 wv = *reinterpret_cast<const float4*>(&Ws[k * WPITCH + lane * 4]);
#pragma unroll
            for (int j = 0; j < 8; j++) {
                float xv = Xs[((wp << 3) + j) * FDIM + k];
                acc[j][0] = fmaf(xv, wv.x, acc[j][0]);
                acc[j][1] = fmaf(xv, wv.y, acc[j][1]);
                acc[j][2] = fmaf(xv, wv.z, acc[j][2]);
                acc[j][3] = fmaf(xv, wv.w, acc[j][3]);
            }
        }
#pragma unroll
        for (int j = 0; j < 8; j++) {
            int node = n0 + (wp << 3) + j;
            float4 r;
            r.x = fmaxf(acc[j][0], 0.f);
            r.y = fmaxf(acc[j][1], 0.f);
            r.z = fmaxf(acc[j][2], 0.f);
            r.w = fmaxf(acc[j][3], 0.f);
            *reinterpret_cast<float4*>(&hout[node * FDIM + lane * 4]) = r;
        }
    }
}

// Final classifier: out = h2 @ Wo^T + bo
__global__ void __launch_bounds__(256)
out_kernel(const float4* __restrict__ h2,
           const float* __restrict__ Wo, const float* __restrict__ bo,
           float* __restrict__ out, int n) {
    __shared__ float Wos[FDIM * 32];
    int tid = threadIdx.x;
    for (int i = tid; i < 32 * FDIM; i += 256) {
        int o = i >> 7, k = i & 127;
        Wos[k * 32 + o] = Wo[i];
    }
    __syncthreads();

    int lane = tid & 31;
    int wp   = tid >> 5;
    float bias = bo[lane];
    for (int node = blockIdx.x * 8 + wp; node < n; node += gridDim.x * 8) {
        float4 x = h2[node * 32 + lane];
        float acc = bias;
#pragma unroll
        for (int j = 0; j < 32; j++) {
            float a = __shfl_sync(0xffffffffu, x.x, j);
            float b = __shfl_sync(0xffffffffu, x.y, j);
            float c = __shfl_sync(0xffffffffu, x.z, j);
            float d = __shfl_sync(0xffffffffu, x.w, j);
            int k = j << 2;
            acc += a * Wos[(k + 0) * 32 + lane];
            acc += b * Wos[(k + 1) * 32 + lane];
            acc += c * Wos[(k + 2) * 32 + lane];
            acc += d * Wos[(k + 3) * 32 + lane];
        }
        out[node * 32 + lane] = acc;
    }
}

// ---------------------------------------------------------------------------
extern "C" void kernel_launch(void* const* d_in, const int* in_sizes, int n_in,
                              void* d_out, int out_size) {
    const float* features = (const float*)d_in[0];
    const int*   src      = (const int*)  d_in[1];
    const int*   dst      = (const int*)  d_in[2];
    const float* weight   = (const float*)d_in[3];
    const float* W1       = (const float*)d_in[4];
    const float* b1       = (const float*)d_in[5];
    const float* W2       = (const float*)d_in[6];
    const float* b2       = (const float*)d_in[7];
    const float* Wo       = (const float*)d_in[8];
    const float* bo       = (const float*)d_in[9];
    float* out = (float*)d_out;

    int N = in_sizes[0] / FDIM;
    int E = in_sizes[1];

    void *pX_v, *ph1_v, *ph2_v, *ppack_v;
    cudaGetSymbolAddress(&pX_v,  g_X);
    cudaGetSymbolAddress(&ph1_v, g_h1);
    cudaGetSymbolAddress(&ph2_v, g_h2);
    cudaGetSymbolAddress(&ppack_v, g_pack);
    float* pX  = (float*)pX_v;
    float* ph1 = (float*)ph1_v;
    float* ph2 = (float*)ph2_v;

    const int smem_bytes = (FDIM * WPITCH + TM * FDIM) * (int)sizeof(float);
    cudaFuncSetAttribute(update_kernel,
                         cudaFuncAttributeMaxDynamicSharedMemorySize, smem_bytes);

    int nb = (N + SCAN_BLK - 1) / SCAN_BLK;

    // CSR build (shared by both layers)
    cudaMemsetAsync(ppack_v, 0, N * sizeof(unsigned long long));
    edge_stats_kernel<<<(E + 255) / 256, 256>>>(dst, weight, E);
    scan_partial_kernel<<<nb, SCAN_BLK>>>(N);
    scan_top_kernel<<<1, MAX_PART>>>(nb, N);
    scan_emit_kernel<<<nb, SCAN_BLK>>>(N);
    scatter_kernel<<<(E + 255) / 256, 256>>>(src, dst, weight, E);

    int agg_grid = (N * 32 + 255) / 256;
    int upd_grid = 296;

    // Layer 1
    agg_csr_kernel<<<agg_grid, 256>>>((const float4*)features, (float4*)pX, N);
    update_kernel<<<upd_grid, 256, smem_bytes>>>((const float4*)pX, W1, b1, ph1, N);

    // Layer 2
    agg_csr_kernel<<<agg_grid, 256>>>((const float4*)ph1, (float4*)pX, N);
    update_kernel<<<upd_grid, 256, smem_bytes>>>((const float4*)pX, W2, b2, ph2, N);

    // Classifier
    out_kernel<<<2048, 256>>>((const float4*)ph2, Wo, bo, out, N);
}